// round 5
// baseline (speedup 1.0000x reference)
#include <cuda_runtime.h>
#include <cstdint>

#define N_NODES 200000
#define HID 32

// ---------------- scratch (static device globals; no allocation) ----------
__device__ int   g_deg[N_NODES];
__device__ float g_dinv[N_NODES];
__device__ float g_acc1[N_NODES];
__device__ float g_h2 [N_NODES * HID];
__device__ float g_acc2[N_NODES * HID];
__device__ float g_x2 [N_NODES * HID];

// ---------------- GCN stages ------------------------------------------------
__global__ void k_init(const float* __restrict__ ec, float* __restrict__ out_edge, int E) {
    int i = blockIdx.x * blockDim.x + threadIdx.x;
    if (i < N_NODES * HID) g_acc2[i] = 0.f;
    if (i < N_NODES) { g_deg[i] = 0; g_acc1[i] = 0.f; }
    if (i < E) out_edge[i] = ec[i];
}
__global__ void k_deg(const int* __restrict__ dst, int E) {
    int e = blockIdx.x * blockDim.x + threadIdx.x;
    if (e < E) atomicAdd(&g_deg[dst[e]], 1);
}
__global__ void k_dinv() {
    int n = blockIdx.x * blockDim.x + threadIdx.x;
    if (n < N_NODES) g_dinv[n] = rsqrtf((float)(g_deg[n] + 1));
}
__global__ void k_acc1(const int* __restrict__ src, const int* __restrict__ dst, int E) {
    int e = blockIdx.x * blockDim.x + threadIdx.x;
    if (e < E) atomicAdd(&g_acc1[dst[e]], g_dinv[src[e]]);
}
__global__ void k_node1(const float* __restrict__ W1, const float* __restrict__ b1,
                        const float* __restrict__ W2) {
    __shared__ float sW1[HID], sB1[HID], sW2[HID * HID];
    for (int i = threadIdx.x; i < HID; i += blockDim.x) { sW1[i] = W1[i]; sB1[i] = b1[i]; }
    for (int i = threadIdx.x; i < HID * HID; i += blockDim.x) sW2[i] = W2[i];
    __syncthreads();
    int n = blockIdx.x * blockDim.x + threadIdx.x;
    if (n >= N_NODES) return;
    float dv = g_dinv[n];
    float s1 = dv * (g_acc1[n] + dv);
    float x1[HID];
#pragma unroll
    for (int k = 0; k < HID; k++) x1[k] = fmaxf(fmaf(sW1[k], s1, sB1[k]), 0.f);
    float h2[HID];
#pragma unroll
    for (int j = 0; j < HID; j++) h2[j] = 0.f;
#pragma unroll
    for (int i = 0; i < HID; i++) {
        float xi = x1[i];
#pragma unroll
        for (int j = 0; j < HID; j++) h2[j] = fmaf(xi, sW2[i * HID + j], h2[j]);
    }
    float4* o = (float4*)(g_h2 + (size_t)n * HID);
#pragma unroll
    for (int q = 0; q < 8; q++)
        o[q] = make_float4(h2[4 * q], h2[4 * q + 1], h2[4 * q + 2], h2[4 * q + 3]);
}
__global__ void k_msg(const int* __restrict__ src, const int* __restrict__ dst, int E) {
    int idx = blockIdx.x * blockDim.x + threadIdx.x;
    int e = idx >> 5, k = idx & 31;
    if (e >= E) return;
    int s = src[e], d = dst[e];
    float nrm = g_dinv[s] * g_dinv[d];
    atomicAdd(&g_acc2[(size_t)d * HID + k], g_h2[(size_t)s * HID + k] * nrm);
}
__global__ void k_node2(const float* __restrict__ b2) {
    int i = blockIdx.x * blockDim.x + threadIdx.x;
    if (i >= N_NODES * HID) return;
    int n = i >> 5, k = i & 31;
    float dv = g_dinv[n];
    g_x2[i] = fmaxf(g_acc2[i] + g_h2[i] * dv * dv + b2[k], 0.f);
}

// ---------------- stage 7: triangle MLP on tensor cores ---------------------
#define WPB  4
#define TILE 16
#define SAS  44
// smem float offsets
#define OFF_W1F 0                       // 5*8*32 uint2 = 2560 floats
#define OFF_W2F 2560                    // 8*4*32 uint2 = 2048 floats
#define OFF_B1  4608
#define OFF_B2  4672
#define OFF_W3  4704                    // 96
#define OFF_B3  4800                    // 4
#define OFF_WARP 4804                   // 16B aligned (4804*4 = 19216)
#define WARP_FLOATS (TILE * SAS)        // 704
#define SMEM_FLOATS (OFF_WARP + WPB * WARP_FLOATS)   // 7620 -> 30480 B (static)

__device__ __forceinline__ uint32_t f2tf(float x) {
    uint32_t r; asm("cvt.rna.tf32.f32 %0,%1;" : "=r"(r) : "f"(x)); return r;
}
__device__ __forceinline__ void mma_tf32(
    float& c0, float& c1, float& c2, float& c3,
    uint32_t a0, uint32_t a1, uint32_t a2, uint32_t a3,
    uint32_t b0, uint32_t b1)
{
    asm volatile(
        "mma.sync.aligned.m16n8k8.row.col.f32.tf32.tf32.f32 "
        "{%0,%1,%2,%3},{%4,%5,%6,%7},{%8,%9},{%0,%1,%2,%3};"
        : "+f"(c0), "+f"(c1), "+f"(c2), "+f"(c3)
        : "r"(a0), "r"(a1), "r"(a2), "r"(a3), "r"(b0), "r"(b1));
}

__global__ void __launch_bounds__(WPB * 32, 4) k_tri(
    const float* __restrict__ t12, const float* __restrict__ t13, const float* __restrict__ t23,
    const int* __restrict__ c12, const int* __restrict__ c13, const int* __restrict__ c23,
    const float* __restrict__ ec,
    const float* __restrict__ Wm1, const float* __restrict__ bm1,
    const float* __restrict__ Wm2, const float* __restrict__ bm2,
    const float* __restrict__ Wm3, const float* __restrict__ bm3,
    float* __restrict__ out_edge,
    float* __restrict__ o12, float* __restrict__ o13, float* __restrict__ o23, int T)
{
    __shared__ float smem[SMEM_FLOATS];
    uint2* sW1f = (uint2*)(smem + OFF_W1F);   // [kt*8+nt][qd*8+grp] = (b_row kt8+qd, kt8+qd+4)
    uint2* sW2f = (uint2*)(smem + OFF_W2F);   // [kt*4+nt][qd*8+grp]
    float* sB1 = smem + OFF_B1;
    float* sB2 = smem + OFF_B2;
    float* sW3 = smem + OFF_W3;
    float* sB3 = smem + OFF_B3;

    const int tid = threadIdx.x;
    const unsigned FULL = 0xffffffffu;

    // ---- pre-fragmented weights (tf32 bits; 1/3 folded into W1 rows 3..34)
    for (int i = tid; i < 5 * 8 * 32; i += blockDim.x) {
        int kt = i >> 8, rem = i & 255, nt = rem >> 5, j = rem & 31;
        int q = j >> 3, g = j & 7;
        int col = nt * 8 + g;
        int r0 = kt * 8 + q, r1 = r0 + 4;
        float v0 = (r0 < 38) ? Wm1[r0 * 64 + col] : 0.f;
        float v1 = (r1 < 38) ? Wm1[r1 * 64 + col] : 0.f;
        if (r0 >= 3 && r0 < 35) v0 *= (1.f / 3.f);
        if (r1 >= 3 && r1 < 35) v1 *= (1.f / 3.f);
        sW1f[i] = make_uint2(f2tf(v0), f2tf(v1));
    }
    for (int i = tid; i < 8 * 4 * 32; i += blockDim.x) {
        int kt = i >> 7, rem = i & 127, nt = rem >> 5, j = rem & 31;
        int q = j >> 3, g = j & 7;
        int col = nt * 8 + g;
        int r0 = kt * 8 + q;
        sW2f[i] = make_uint2(f2tf(Wm2[r0 * 32 + col]), f2tf(Wm2[(r0 + 4) * 32 + col]));
    }
    if (tid < 64) sB1[tid] = bm1[tid];
    if (tid < 32) sB2[tid] = bm2[tid];
    for (int i = tid; i < 96; i += blockDim.x) sW3[i] = Wm3[i];
    if (tid < 4) sB3[tid] = (tid < 3) ? bm3[tid] : 0.f;
    __syncthreads();

    const int wid  = tid >> 5;
    const int lane = tid & 31;
    const int grp  = lane >> 2;   // 0..7
    const int qd   = lane & 3;    // 0..3
    const int fj   = (qd << 3) + grp;          // weight-fragment index within 32
    const int srcA = (grp << 2) + (qd >> 1);   // C->A shuffle source lane
    const bool odd = qd & 1;
    float* sA = smem + OFF_WARP + wid * WARP_FLOATS;   // [16][44]

    const float b30 = sB3[0], b31 = sB3[1], b32 = sB3[2];

    const int ntiles = (T + TILE - 1) / TILE;
    const int gw = blockIdx.x * WPB + wid;
    const int gstride = gridDim.x * WPB;

    for (int tile = gw; tile < ntiles; tile += gstride) {
        const int t0 = tile * TILE;

        // ---- gather phase ------------------------------------------------
        int ia = 0, ib = 0, icx = 0;
        float f12 = 0.f, f13 = 0.f, f23 = 0.f;
        if (lane < TILE) {
            int t = t0 + lane;
            float ea = 0.f, eb = 0.f, ecv = 0.f;
            if (t < T) {
                ia = c12[t]; ib = c13[t]; icx = c23[t];
                f12 = t12[t]; f13 = t13[t]; f23 = t23[t];
                ea = ec[ia]; eb = ec[ib]; ecv = ec[icx];
            }
            float* row = sA + lane * SAS;
            row[0] = f12; row[1] = f13; row[2] = f23;
            row[35] = ea; row[36] = eb; row[37] = ecv;
            row[38] = 0.f; row[39] = 0.f;
        }
#pragma unroll
        for (int half = 0; half < 2; half++) {
            const int base = half * 8;
            int ja[8], jb[8], jc[8];
#pragma unroll
            for (int r = 0; r < 8; r++) {
                ja[r] = __shfl_sync(FULL, ia,  base + r);
                jb[r] = __shfl_sync(FULL, ib,  base + r);
                jc[r] = __shfl_sync(FULL, icx, base + r);
            }
            float va[8], vb[8], vc[8];
#pragma unroll
            for (int r = 0; r < 8; r++) va[r] = g_x2[(size_t)ja[r] * HID + lane];
#pragma unroll
            for (int r = 0; r < 8; r++) vb[r] = g_x2[(size_t)jb[r] * HID + lane];
#pragma unroll
            for (int r = 0; r < 8; r++) vc[r] = g_x2[(size_t)jc[r] * HID + lane];
#pragma unroll
            for (int r = 0; r < 8; r++)
                sA[(base + r) * SAS + 3 + lane] = va[r] + vb[r] + vc[r];  // 1/3 in sW1
        }
        __syncwarp();

        // ---- layer 1: [16x40] @ [40x64] ----------------------------------
        float a1[8][4];
#pragma unroll
        for (int nt = 0; nt < 8; nt++) {
            float2 bb = *(const float2*)(sB1 + nt * 8 + 2 * qd);
            a1[nt][0] = bb.x; a1[nt][1] = bb.y; a1[nt][2] = bb.x; a1[nt][3] = bb.y;
        }
#pragma unroll
        for (int kt = 0; kt < 5; kt++) {
            uint32_t A0 = f2tf(sA[grp * SAS + kt * 8 + qd]);
            uint32_t A1 = f2tf(sA[(grp + 8) * SAS + kt * 8 + qd]);
            uint32_t A2 = f2tf(sA[grp * SAS + kt * 8 + qd + 4]);
            uint32_t A3 = f2tf(sA[(grp + 8) * SAS + kt * 8 + qd + 4]);
#pragma unroll
            for (int nt = 0; nt < 8; nt++) {
                uint2 b = sW1f[(kt * 8 + nt) * 32 + fj];
                mma_tf32(a1[nt][0], a1[nt][1], a1[nt][2], a1[nt][3], A0, A1, A2, A3, b.x, b.y);
            }
        }

        // ---- layer 2: [16x64] @ [64x32], C->A via quad shuffles ----------
        float a2[4][4];
#pragma unroll
        for (int nt = 0; nt < 4; nt++) {
            float2 bb = *(const float2*)(sB2 + nt * 8 + 2 * qd);
            a2[nt][0] = bb.x; a2[nt][1] = bb.y; a2[nt][2] = bb.x; a2[nt][3] = bb.y;
        }
#pragma unroll
        for (int kt = 0; kt < 8; kt++) {
            float r0 = fmaxf(a1[kt][0], 0.f), r1 = fmaxf(a1[kt][1], 0.f);
            float r2 = fmaxf(a1[kt][2], 0.f), r3 = fmaxf(a1[kt][3], 0.f);
            float x0 = __shfl_sync(FULL, r0, srcA),     x1 = __shfl_sync(FULL, r1, srcA);
            float y0 = __shfl_sync(FULL, r2, srcA),     y1 = __shfl_sync(FULL, r3, srcA);
            float z0 = __shfl_sync(FULL, r0, srcA + 2), z1 = __shfl_sync(FULL, r1, srcA + 2);
            float w0 = __shfl_sync(FULL, r2, srcA + 2), w1 = __shfl_sync(FULL, r3, srcA + 2);
            uint32_t H0 = f2tf(odd ? x1 : x0);
            uint32_t H1 = f2tf(odd ? y1 : y0);
            uint32_t H2 = f2tf(odd ? z1 : z0);
            uint32_t H3 = f2tf(odd ? w1 : w0);
#pragma unroll
            for (int nt = 0; nt < 4; nt++) {
                uint2 b = sW2f[(kt * 4 + nt) * 32 + fj];
                mma_tf32(a2[nt][0], a2[nt][1], a2[nt][2], a2[nt][3], H0, H1, H2, H3, b.x, b.y);
            }
        }

        // ---- layer 3: scalar fp32 partial dots + quad reduce -------------
        float dA0 = 0.f, dA1 = 0.f, dA2 = 0.f;   // row grp
        float dB0 = 0.f, dB1 = 0.f, dB2 = 0.f;   // row grp+8
#pragma unroll
        for (int nt = 0; nt < 4; nt++) {
            int c = nt * 8 + 2 * qd;
            float hA0 = fmaxf(a2[nt][0], 0.f), hA1 = fmaxf(a2[nt][1], 0.f);
            float hB0 = fmaxf(a2[nt][2], 0.f), hB1 = fmaxf(a2[nt][3], 0.f);
            float w00 = sW3[c * 3 + 0], w01 = sW3[c * 3 + 1], w02 = sW3[c * 3 + 2];
            float w10 = sW3[c * 3 + 3], w11 = sW3[c * 3 + 4], w12 = sW3[c * 3 + 5];
            dA0 = fmaf(hA0, w00, fmaf(hA1, w10, dA0));
            dA1 = fmaf(hA0, w01, fmaf(hA1, w11, dA1));
            dA2 = fmaf(hA0, w02, fmaf(hA1, w12, dA2));
            dB0 = fmaf(hB0, w00, fmaf(hB1, w10, dB0));
            dB1 = fmaf(hB0, w01, fmaf(hB1, w11, dB1));
            dB2 = fmaf(hB0, w02, fmaf(hB1, w12, dB2));
        }
#pragma unroll
        for (int off = 1; off < 4; off <<= 1) {
            dA0 += __shfl_xor_sync(FULL, dA0, off);
            dA1 += __shfl_xor_sync(FULL, dA1, off);
            dA2 += __shfl_xor_sync(FULL, dA2, off);
            dB0 += __shfl_xor_sync(FULL, dB0, off);
            dB1 += __shfl_xor_sync(FULL, dB1, off);
            dB2 += __shfl_xor_sync(FULL, dB2, off);
        }
        dA0 += b30; dA1 += b31; dA2 += b32;
        dB0 += b30; dB1 += b31; dB2 += b32;

        // route row data to lanes 0..15 (lane l <- quad (l&7), A if l<8 else B)
        int srcl = (lane & 7) << 2;
        float e0A = __shfl_sync(FULL, dA0, srcl), e0B = __shfl_sync(FULL, dB0, srcl);
        float e1A = __shfl_sync(FULL, dA1, srcl), e1B = __shfl_sync(FULL, dB1, srcl);
        float e2A = __shfl_sync(FULL, dA2, srcl), e2B = __shfl_sync(FULL, dB2, srcl);
        float d0 = (lane < 8) ? e0A : e0B;
        float d1 = (lane < 8) ? e1A : e1B;
        float d2 = (lane < 8) ? e2A : e2B;

        // ---- epilogue ----------------------------------------------------
        if (lane < TILE && (t0 + lane) < T) {
            int t = t0 + lane;
            o12[t] = f12 - d0;
            o13[t] = f13 - d1;
            o23[t] = f23 - d2;
            atomicAdd(out_edge + ia,  d0);
            atomicAdd(out_edge + ib,  d1);
            atomicAdd(out_edge + icx, d2);
        }
        __syncwarp();
    }
}

// ---------------- launcher ----------------------------------------------------
extern "C" void kernel_launch(void* const* d_in, const int* in_sizes, int n_in,
                              void* d_out, int out_size) {
    const float* edge_costs = (const float*)d_in[0];
    const float* t12 = (const float*)d_in[1];
    const float* t13 = (const float*)d_in[2];
    const float* t23 = (const float*)d_in[3];
    const int*   c12 = (const int*)d_in[4];
    const int*   c13 = (const int*)d_in[5];
    const int*   c23 = (const int*)d_in[6];
    const int*   eidx = (const int*)d_in[8];
    const float* W1  = (const float*)d_in[10];
    const float* b1  = (const float*)d_in[11];
    const float* W2  = (const float*)d_in[12];
    const float* b2  = (const float*)d_in[13];
    const float* Wm1 = (const float*)d_in[14];
    const float* bm1 = (const float*)d_in[15];
    const float* Wm2 = (const float*)d_in[16];
    const float* bm2 = (const float*)d_in[17];
    const float* Wm3 = (const float*)d_in[18];
    const float* bm3 = (const float*)d_in[19];

    int E = in_sizes[0];       // 200000
    int T = in_sizes[1];       // 2000000
    const int* src = eidx;
    const int* dst = eidx + E;

    float* out_edge = (float*)d_out;
    float* o12 = out_edge + E;
    float* o13 = o12 + T;
    float* o23 = o13 + T;

    const int B = 256;
    k_init <<<(N_NODES * HID + B - 1) / B, B>>>(edge_costs, out_edge, E);
    k_deg  <<<(E + B - 1) / B, B>>>(dst, E);
    k_dinv <<<(N_NODES + B - 1) / B, B>>>();
    k_acc1 <<<(E + B - 1) / B, B>>>(src, dst, E);
    k_node1<<<(N_NODES + B - 1) / B, B>>>(W1, b1, W2);
    k_msg  <<<((size_t)E * 32 + B - 1) / B, B>>>(src, dst, E);
    k_node2<<<(N_NODES * HID + B - 1) / B, B>>>(b2);

    k_tri<<<1184, WPB * 32>>>(t12, t13, t23, c12, c13, c23, edge_costs,
                              Wm1, bm1, Wm2, bm2, Wm3, bm3,
                              out_edge, o12, o13, o23, T);
}